// round 1
// baseline (speedup 1.0000x reference)
#include <cuda_runtime.h>
#include <cstdint>
#include <float.h>
#include <limits.h>

// Problem constants (fixed shapes for this problem)
#define B_    8
#define C_    16
#define F_    256
#define H_    112
#define W_    112
#define NCELL (B_ * C_)       // 128
#define W4_   (W_ / 4)        // 28 float4 per feature row

// Compact mask scratch: bbox width padded to mult of 4, max bw = 35 -> x-align pad -> <= 40
#define MAXBW 40
#define MAXBH 36
#define CMSTRIDE (MAXBW * MAXBH)   // 1440 floats per cell

// dtype flag for cell_masks buffer: 0 = int32 (0/1), bit0 = uint8 bytes, bit1 = float32 (0.0/1.0)
__device__ int g_dtype_flag;

// Per-cell header: y0, szy(bh), x0a, bwa, x0off(x0-x0a), szx
__device__ int g_hdr[NCELL][8];

// Per-cell compact float mask (1.0 masked / 0.0 not), row stride = bwa (packed)
__device__ __align__(16) float g_cmask[NCELL][CMSTRIDE];

// ---------------------------------------------------------------------------
// K0: reset detection flag
__global__ void init_flag_k() { g_dtype_flag = 0; }

// K1: detect mask dtype by byte pattern.
// Scan the first nmask BYTES (safe for all candidate dtypes) as u32 words:
//   int32 0/1   -> words in {0,1}: no high bytes set
//   float 0/1.0 -> words in {0, 0x3F800000}
//   uint8 0/1   -> packed 00/01 bytes: high bytes set, never == 0x3F800000
__global__ void detect_k(const unsigned int* __restrict__ m, int nwords) {
    int r = 0;
    for (int i = blockIdx.x * blockDim.x + threadIdx.x; i < nwords;
         i += gridDim.x * blockDim.x) {
        unsigned int w = m[i];
        if (w == 0x3F800000u)       r |= 2;
        else if (w & 0xFFFFFF00u)   r |= 1;
    }
    // reduce within warp to limit atomics
    for (int o = 16; o > 0; o >>= 1) r |= __shfl_xor_sync(0xffffffffu, r, o);
    if ((threadIdx.x & 31) == 0 && r) atomicOr(&g_dtype_flag, r);
}

// ---------------------------------------------------------------------------
// K2: per-cell bbox + compact float mask. One block per cell.
__global__ void __launch_bounds__(256) prep_k(const void* __restrict__ mask) {
    const int cell = blockIdx.x;
    const int t = threadIdx.x;
    const int flag = g_dtype_flag;

    const uint8_t* mb = (const uint8_t*)mask + (size_t)cell * (H_ * W_);
    const int*     mi = (const int*)mask     + (size_t)cell * (H_ * W_);
    const float*   mf = (const float*)mask   + (size_t)cell * (H_ * W_);

    __shared__ int sy0, sy1, sx0, sx1;
    if (t == 0) { sy0 = INT_MAX; sy1 = -1; sx0 = INT_MAX; sx1 = -1; }
    __syncthreads();

    int ly0 = INT_MAX, ly1 = -1, lx0 = INT_MAX, lx1 = -1;
    for (int p = t; p < H_ * W_; p += 256) {
        bool set;
        if (flag & 1)      set = (mb[p] != 0);
        else if (flag & 2) set = (mf[p] != 0.0f);
        else               set = (mi[p] != 0);
        if (set) {
            int y = p / W_, x = p - y * W_;
            ly0 = min(ly0, y); ly1 = max(ly1, y);
            lx0 = min(lx0, x); lx1 = max(lx1, x);
        }
    }
    if (ly1 >= 0) {
        atomicMin(&sy0, ly0); atomicMax(&sy1, ly1);
        atomicMin(&sx0, lx0); atomicMax(&sx1, lx1);
    }
    __syncthreads();

    const int y0 = sy0, y1 = sy1 + 1, x0 = sx0, x1 = sx1 + 1;
    const int x0a = x0 & ~3;
    const int bwa = (x1 - x0a + 3) & ~3;
    const int bh  = y1 - y0;

    if (t == 0) {
        g_hdr[cell][0] = y0;
        g_hdr[cell][1] = bh;        // szy
        g_hdr[cell][2] = x0a;
        g_hdr[cell][3] = bwa;
        g_hdr[cell][4] = x0 - x0a;  // x0off
        g_hdr[cell][5] = x1 - x0;   // szx
    }

    // Compact float mask; pad columns read real mask (guaranteed 0 outside bbox cols)
    const int ntot = bh * bwa;
    for (int p = t; p < ntot; p += 256) {
        int r = p / bwa, c = p - r * bwa;
        int gp = (y0 + r) * W_ + (x0a + c);
        bool set;
        if (flag & 1)      set = (mb[gp] != 0);
        else if (flag & 2) set = (mf[gp] != 0.0f);
        else               set = (mi[gp] != 0);
        g_cmask[cell][p] = set ? 1.0f : 0.0f;
    }
}

// ---------------------------------------------------------------------------
// K3: main pooling. grid = (NCELL, F_/8), block = 256 (8 warps, 1 feature/warp).
// Per warp: lanes tile (row, float4-group) over the bbox; y-bins are outer
// phases (fixed-register accumulators); x-binning resolved at the final merge.
__global__ void __launch_bounds__(256) pool_k(const float* __restrict__ feat,
                                              float* __restrict__ out) {
    const int cell = blockIdx.x;
    const int warp = threadIdx.x >> 5;
    const int lane = threadIdx.x & 31;
    const int f = blockIdx.y * 8 + warp;

    const int y0    = g_hdr[cell][0];
    const int szy   = g_hdr[cell][1];
    const int x0a   = g_hdr[cell][2];
    const int bwa   = g_hdr[cell][3];
    const int x0off = g_hdr[cell][4];
    const int szx   = g_hdr[cell][5];

    __shared__ __align__(16) float smask[CMSTRIDE];
    {
        const int ntot = szy * bwa;  // multiple of 4
        const float4* src = (const float4*)g_cmask[cell];
        float4* dst = (float4*)smask;
        for (int p = threadIdx.x; p * 4 < ntot; p += 256) dst[p] = src[p];
    }
    __syncthreads();

    const int nG  = bwa >> 2;        // float4 groups per row: 3..10
    const int rpi = 32 / nG;         // rows per iteration: 3..10
    const int rowoff = lane / nG;
    const int g = lane - rowoff * nG;
    const bool active = (rowoff < rpi);

    const int b = cell >> 4;         // cell = b*C + c
    const float4* fbase = (const float4*)feat
        + (size_t)((b * F_ + f) * H_ + y0) * W4_ + (x0a >> 2) + g;
    const float4* mbase = (const float4*)smask + g;
    const int fstep = rpi * W4_;
    const int mstep = rpi * nG;

    float bins[9];

#pragma unroll
    for (int i = 0; i < 3; i++) {
        const int ys = (i * szy) / 3;
        const int ye = ((i + 1) * szy + 2) / 3;   // ceil
        float a0 = -FLT_MAX, a1 = -FLT_MAX, a2 = -FLT_MAX, a3 = -FLT_MAX;
        if (active) {
            const float4* fp = fbase + (ys + rowoff) * W4_;
            const float4* mp = mbase + (ys + rowoff) * nG;
            for (int r = ys + rowoff; r < ye; r += rpi, fp += fstep, mp += mstep) {
                const float4 fv = __ldg(fp);
                const float4 mv = *mp;
                a0 = fmaxf(a0, fv.x * mv.x);
                a1 = fmaxf(a1, fv.y * mv.y);
                a2 = fmaxf(a2, fv.z * mv.z);
                a3 = fmaxf(a3, fv.w * mv.w);
            }
        }
        // merge this y-phase's 4 columns into x-bins by membership
#pragma unroll
        for (int j = 0; j < 3; j++) {
            float tb = -FLT_MAX;
#pragma unroll
            for (int k = 0; k < 4; k++) {
                const int relx = g * 4 + k - x0off;
                const bool mem = (3 * relx >= j * szx - 2) && (3 * relx < (j + 1) * szx);
                const float av = (k == 0) ? a0 : (k == 1) ? a1 : (k == 2) ? a2 : a3;
                if (mem) tb = fmaxf(tb, av);
            }
            bins[i * 3 + j] = tb;
        }
    }

    // warp max-reduce all 9 bins (inactive/pad lanes hold -FLT_MAX)
#pragma unroll
    for (int q = 0; q < 9; q++) {
        float v = bins[q];
#pragma unroll
        for (int o = 16; o > 0; o >>= 1)
            v = fmaxf(v, __shfl_xor_sync(0xffffffffu, v, o));
        bins[q] = v;
    }

    if (lane == 0) {
        float* o = out + (size_t)cell * (F_ * 9) + f * 9;
#pragma unroll
        for (int q = 0; q < 9; q++) o[q] = bins[q];
    }
}

// ---------------------------------------------------------------------------
extern "C" void kernel_launch(void* const* d_in, const int* in_sizes, int n_in,
                              void* d_out, int out_size) {
    const float* feat = (const float*)d_in[0];
    const void*  mask = d_in[1];
    // d_in[2] = cell_counts (always C per batch) — unused
    float* out = (float*)d_out;

    const int nmask = in_sizes[1];          // logical element count = NCELL*H*W
    const int nwords = nmask / 4;           // safe byte range for all dtypes

    init_flag_k<<<1, 1>>>();
    detect_k<<<96, 256>>>((const unsigned int*)mask, nwords);
    prep_k<<<NCELL, 256>>>(mask);

    dim3 grid(NCELL, F_ / 8);
    pool_k<<<grid, 256>>>(feat, out);
}

// round 3
// speedup vs baseline: 1.1720x; 1.1720x over previous
#include <cuda_runtime.h>
#include <cstdint>
#include <float.h>
#include <limits.h>

// Problem constants (fixed shapes)
#define B_    8
#define C_    16
#define F_    256
#define H_    112
#define W_    112
#define NCELL (B_ * C_)       // 128
#define W4_   (W_ / 4)        // 28 float4 per feature row
#define PXPC  (H_ * W_)       // 12544 pixels per cell

// Compact mask scratch bounds: bbox w <= 35, +3 align +3 pad -> <= 40; h <= 35
#define MAXBW 40
#define MAXBH 36
#define CMSTRIDE (MAXBW * MAXBH)

// Per-cell header: y0, szy, x0a, bwa, x0off, szx
__device__ int g_hdr[NCELL][8];
// Per-cell compact float mask (1.0 / 0.0), row stride bwa, 16B aligned rows
__device__ __align__(16) float g_cmask[NCELL][CMSTRIDE];

// ---------------------------------------------------------------------------
// Fused prep: per-cell dtype detect + bbox + compact float mask. 1 block/cell.
//
// dtype detection is per-block-local and safe: every cell has a solid 5x5 core,
// so under uint8 the cell's own 12544-byte window contains packed-01 words
// (high bytes set, != 0x3F800000) -> flag=1. Under int32 OR float32, words are
// {0,1} or {0,0x3F800000} -> flag=0, and the 4-byte path treats "word != 0" as
// set, which is correct for both encodings.
__global__ void __launch_bounds__(256) prep_k(const void* __restrict__ mask) {
    const int cell = blockIdx.x;
    const int t = threadIdx.x;

    __shared__ int sy0, sy1, sx0, sx1;
    if (t == 0) { sy0 = INT_MAX; sy1 = -1; sx0 = INT_MAX; sx1 = -1; }

    // --- detect over this cell's 12544-byte window (784 uint4) ---
    int r = 0;
    {
        const uint4* wq = (const uint4*)mask + (size_t)cell * 784;
        for (int i = t; i < 784; i += 256) {
            uint4 w = wq[i];
            if ((w.x != 0x3F800000u && (w.x & 0xFFFFFF00u)) ||
                (w.y != 0x3F800000u && (w.y & 0xFFFFFF00u)) ||
                (w.z != 0x3F800000u && (w.z & 0xFFFFFF00u)) ||
                (w.w != 0x3F800000u && (w.w & 0xFFFFFF00u))) r = 1;
        }
    }
    const int flag = __syncthreads_or(r);   // also orders the smem init above

    // --- bbox scan ---
    int ly0 = INT_MAX, ly1 = -1, lx0 = INT_MAX, lx1 = -1;
    if (flag) {
        // uint8: 784 uint4 = 16 px each; 112 % 16 == 0 -> one row per vector
        const uint4* mq = (const uint4*)mask + (size_t)cell * 784;
        for (int i = t; i < 784; i += 256) {
            uint4 w = mq[i];
            if (w.x | w.y | w.z | w.w) {
                int p = i * 16, y = p / W_, xb = p % W_;
                ly0 = min(ly0, y); ly1 = max(ly1, y);
                unsigned int comp[4] = {w.x, w.y, w.z, w.w};
#pragma unroll
                for (int c = 0; c < 4; c++) {
#pragma unroll
                    for (int k = 0; k < 4; k++) {
                        if ((comp[c] >> (k * 8)) & 0xFFu) {
                            int x = xb + c * 4 + k;
                            lx0 = min(lx0, x); lx1 = max(lx1, x);
                        }
                    }
                }
            }
        }
    } else {
        // 4-byte: 3136 uint4 = 4 px each; 112 % 4 == 0 -> one row per vector
        const uint4* mq = (const uint4*)mask + (size_t)cell * 3136;
        for (int i = t; i < 3136; i += 256) {
            uint4 w = mq[i];
            if (w.x | w.y | w.z | w.w) {
                int p = i * 4, y = p / W_, xb = p % W_;
                ly0 = min(ly0, y); ly1 = max(ly1, y);
                if (w.x) { lx0 = min(lx0, xb);     lx1 = max(lx1, xb);     }
                if (w.y) { lx0 = min(lx0, xb + 1); lx1 = max(lx1, xb + 1); }
                if (w.z) { lx0 = min(lx0, xb + 2); lx1 = max(lx1, xb + 2); }
                if (w.w) { lx0 = min(lx0, xb + 3); lx1 = max(lx1, xb + 3); }
            }
        }
    }
    if (ly1 >= 0) {
        atomicMin(&sy0, ly0); atomicMax(&sy1, ly1);
        atomicMin(&sx0, lx0); atomicMax(&sx1, lx1);
    }
    __syncthreads();

    const int y0 = sy0, y1 = sy1 + 1, x0 = sx0, x1 = sx1 + 1;
    const int x0a = x0 & ~3;
    const int bwa = (x1 - x0a + 3) & ~3;
    const int bh  = y1 - y0;

    if (t == 0) {
        g_hdr[cell][0] = y0;
        g_hdr[cell][1] = bh;
        g_hdr[cell][2] = x0a;
        g_hdr[cell][3] = bwa;
        g_hdr[cell][4] = x0 - x0a;
        g_hdr[cell][5] = x1 - x0;
    }

    // --- compact float mask (pad cols read real data; excluded by membership) ---
    const int ntot = bh * bwa;
    const uint8_t* mb = (const uint8_t*)mask + (size_t)cell * PXPC;
    const int*     mi = (const int*)mask     + (size_t)cell * PXPC;
    for (int p = t; p < ntot; p += 256) {
        int rr = p / bwa, c = p - rr * bwa;
        int gp = (y0 + rr) * W_ + (x0a + c);
        bool set = flag ? (mb[gp] != 0) : (mi[gp] != 0);
        g_cmask[cell][p] = set ? 1.0f : 0.0f;
    }
}

// ---------------------------------------------------------------------------
// Main pooling. grid=(NCELL, F/16), block=256 (8 warps, 2 features per warp,
// 16 lanes per feature). Lanes of each half-warp tile (row, float4-group) of
// the bbox; 3 y-bin phases with register accumulators; x-bins resolved at the
// merge. Final reduction: 4-stage shfl butterfly confined to each half-warp,
// reducing BOTH features of a warp simultaneously (18 shfl+fmax per feature
// instead of 45).
__global__ void __launch_bounds__(256) pool_k(const float* __restrict__ feat,
                                              float* __restrict__ out) {
    const int cell = blockIdx.x;
    const int warp = threadIdx.x >> 5;
    const int lane = threadIdx.x & 31;
    const int half = lane >> 4;        // which feature within the warp
    const int hlane = lane & 15;       // lane within the 16-lane feature group
    const int f = blockIdx.y * 16 + warp * 2 + half;

    const int y0    = g_hdr[cell][0];
    const int szy   = g_hdr[cell][1];
    const int x0a   = g_hdr[cell][2];
    const int bwa   = g_hdr[cell][3];
    const int x0off = g_hdr[cell][4];
    const int szx   = g_hdr[cell][5];

    const int nG  = bwa >> 2;          // float4 groups per row: 3..10
    const int rpi = 16 / nG;           // rows per iteration: 1..5
    const int rowoff = hlane / nG;
    const int g = hlane - rowoff * nG;
    const bool active = (rowoff < rpi);

    const int b = cell >> 4;
    const float4* fbase = (const float4*)feat
        + (size_t)((b * F_ + f) * H_ + y0) * W4_ + (x0a >> 2) + g;
    const float4* mbase = (const float4*)g_cmask[cell] + g;
    const int fstep = rpi * W4_;
    const int mstep = rpi * nG;

    // x-bin membership per (bin j, col k) — phase-invariant
    bool mem[12];
#pragma unroll
    for (int j = 0; j < 3; j++)
#pragma unroll
        for (int k = 0; k < 4; k++) {
            const int relx = g * 4 + k - x0off;
            mem[j * 4 + k] = (3 * relx >= j * szx - 2) && (3 * relx < (j + 1) * szx);
        }

    float bins[9];

#pragma unroll
    for (int i = 0; i < 3; i++) {
        const int ys = (i * szy) / 3;
        const int ye = ((i + 1) * szy + 2) / 3;   // ceil (bins may share a row)
        float a0 = -FLT_MAX, a1 = -FLT_MAX, a2 = -FLT_MAX, a3 = -FLT_MAX;
        if (active) {
            const float4* fp = fbase + (ys + rowoff) * W4_;
            const float4* mp = mbase + (ys + rowoff) * nG;
            for (int rr = ys + rowoff; rr < ye; rr += rpi, fp += fstep, mp += mstep) {
                const float4 fv = __ldg(fp);
                const float4 mv = __ldg(mp);
                a0 = fmaxf(a0, fv.x * mv.x);
                a1 = fmaxf(a1, fv.y * mv.y);
                a2 = fmaxf(a2, fv.z * mv.z);
                a3 = fmaxf(a3, fv.w * mv.w);
            }
        }
#pragma unroll
        for (int j = 0; j < 3; j++) {
            float tb = -FLT_MAX;
            if (mem[j * 4 + 0]) tb = fmaxf(tb, a0);
            if (mem[j * 4 + 1]) tb = fmaxf(tb, a1);
            if (mem[j * 4 + 2]) tb = fmaxf(tb, a2);
            if (mem[j * 4 + 3]) tb = fmaxf(tb, a3);
            bins[i * 3 + j] = tb;
        }
    }

    // 4-stage butterfly within each half-warp: reduces both features at once
#pragma unroll
    for (int q = 0; q < 9; q++) {
        float v = bins[q];
#pragma unroll
        for (int o = 8; o > 0; o >>= 1)
            v = fmaxf(v, __shfl_xor_sync(0xffffffffu, v, o));
        bins[q] = v;
    }

    if (hlane < 9) {
        float v = bins[0];
#pragma unroll
        for (int q = 1; q < 9; q++)
            if (hlane == q) v = bins[q];
        out[(size_t)cell * (F_ * 9) + f * 9 + hlane] = v;
    }
}

// ---------------------------------------------------------------------------
extern "C" void kernel_launch(void* const* d_in, const int* in_sizes, int n_in,
                              void* d_out, int out_size) {
    const float* feat = (const float*)d_in[0];
    const void*  mask = d_in[1];
    float* out = (float*)d_out;

    prep_k<<<NCELL, 256>>>(mask);
    dim3 grid(NCELL, F_ / 16);
    pool_k<<<grid, 256>>>(feat, out);
}

// round 4
// speedup vs baseline: 1.2329x; 1.0519x over previous
#include <cuda_runtime.h>
#include <cstdint>
#include <float.h>
#include <limits.h>

// Problem constants (fixed shapes)
#define B_    8
#define C_    16
#define F_    256
#define H_    112
#define W_    112
#define NCELL (B_ * C_)       // 128
#define W4_   (W_ / 4)        // 28 float4 per feature row
#define PXPC  (H_ * W_)       // 12544 pixels per cell

// Compact mask scratch bounds: bbox w <= 35, +3 align +3 pad -> <= 40; h <= 35
#define MAXBW 40
#define MAXBH 36
#define CMSTRIDE (MAXBW * MAXBH)   // 1440 floats

// Per-cell header: y0, szy, x0a, bwa, x0off, szx
__device__ int g_hdr[NCELL][8];
// Per-cell compact float mask (1.0 / 0.0), row stride bwa, 16B aligned rows
__device__ __align__(16) float g_cmask[NCELL][CMSTRIDE];

// ---------------------------------------------------------------------------
// Fused prep: per-cell dtype detect + bbox + compact float mask. 1 block/cell.
//
// dtype detection is per-block-local and safe: every cell has a solid 5x5 core,
// so under uint8 the cell's own 12544-byte window contains packed-01 words
// (high bytes set, != 0x3F800000) -> flag=1. Under int32 OR float32, words are
// {0,1} or {0,0x3F800000} -> flag=0, and the 4-byte path treats "word != 0" as
// set, which is correct for both encodings.
__global__ void __launch_bounds__(256) prep_k(const void* __restrict__ mask) {
    const int cell = blockIdx.x;
    const int t = threadIdx.x;

    __shared__ int sy0, sy1, sx0, sx1;
    if (t == 0) { sy0 = INT_MAX; sy1 = -1; sx0 = INT_MAX; sx1 = -1; }

    // --- detect over this cell's 12544-byte window (784 uint4) ---
    int r = 0;
    {
        const uint4* wq = (const uint4*)mask + (size_t)cell * 784;
        for (int i = t; i < 784; i += 256) {
            uint4 w = wq[i];
            if ((w.x != 0x3F800000u && (w.x & 0xFFFFFF00u)) ||
                (w.y != 0x3F800000u && (w.y & 0xFFFFFF00u)) ||
                (w.z != 0x3F800000u && (w.z & 0xFFFFFF00u)) ||
                (w.w != 0x3F800000u && (w.w & 0xFFFFFF00u))) r = 1;
        }
    }
    const int flag = __syncthreads_or(r);   // also orders the smem init above

    // --- bbox scan ---
    int ly0 = INT_MAX, ly1 = -1, lx0 = INT_MAX, lx1 = -1;
    if (flag) {
        // uint8: 784 uint4 = 16 px each; 112 % 16 == 0 -> one row per vector
        const uint4* mq = (const uint4*)mask + (size_t)cell * 784;
        for (int i = t; i < 784; i += 256) {
            uint4 w = mq[i];
            if (w.x | w.y | w.z | w.w) {
                int p = i * 16, y = p / W_, xb = p % W_;
                ly0 = min(ly0, y); ly1 = max(ly1, y);
                unsigned int comp[4] = {w.x, w.y, w.z, w.w};
#pragma unroll
                for (int c = 0; c < 4; c++) {
#pragma unroll
                    for (int k = 0; k < 4; k++) {
                        if ((comp[c] >> (k * 8)) & 0xFFu) {
                            int x = xb + c * 4 + k;
                            lx0 = min(lx0, x); lx1 = max(lx1, x);
                        }
                    }
                }
            }
        }
    } else {
        // 4-byte: 3136 uint4 = 4 px each; 112 % 4 == 0 -> one row per vector
        const uint4* mq = (const uint4*)mask + (size_t)cell * 3136;
        for (int i = t; i < 3136; i += 256) {
            uint4 w = mq[i];
            if (w.x | w.y | w.z | w.w) {
                int p = i * 4, y = p / W_, xb = p % W_;
                ly0 = min(ly0, y); ly1 = max(ly1, y);
                if (w.x) { lx0 = min(lx0, xb);     lx1 = max(lx1, xb);     }
                if (w.y) { lx0 = min(lx0, xb + 1); lx1 = max(lx1, xb + 1); }
                if (w.z) { lx0 = min(lx0, xb + 2); lx1 = max(lx1, xb + 2); }
                if (w.w) { lx0 = min(lx0, xb + 3); lx1 = max(lx1, xb + 3); }
            }
        }
    }
    if (ly1 >= 0) {
        atomicMin(&sy0, ly0); atomicMax(&sy1, ly1);
        atomicMin(&sx0, lx0); atomicMax(&sx1, lx1);
    }
    __syncthreads();

    const int y0 = sy0, y1 = sy1 + 1, x0 = sx0, x1 = sx1 + 1;
    const int x0a = x0 & ~3;
    const int bwa = (x1 - x0a + 3) & ~3;
    const int bh  = y1 - y0;

    if (t == 0) {
        g_hdr[cell][0] = y0;
        g_hdr[cell][1] = bh;
        g_hdr[cell][2] = x0a;
        g_hdr[cell][3] = bwa;
        g_hdr[cell][4] = x0 - x0a;
        g_hdr[cell][5] = x1 - x0;
    }

    // --- compact float mask (pad cols read real data; excluded by membership) ---
    const int ntot = bh * bwa;
    const uint8_t* mb = (const uint8_t*)mask + (size_t)cell * PXPC;
    const int*     mi = (const int*)mask     + (size_t)cell * PXPC;
    for (int p = t; p < ntot; p += 256) {
        int rr = p / bwa, c = p - rr * bwa;
        int gp = (y0 + rr) * W_ + (x0a + c);
        bool set = flag ? (mb[gp] != 0) : (mi[gp] != 0);
        g_cmask[cell][p] = set ? 1.0f : 0.0f;
    }
}

// ---------------------------------------------------------------------------
// Main pooling. grid=(NCELL, F/16), block=256 (8 warps, 2 features per warp,
// 16 lanes per feature). Compact mask staged ONCE per block into shared mem
// (LDS pipe, 29cyc) so the inner loop's only L1tex traffic is the feature
// load. 3 y-bin phases with register accumulators; x-bins resolved at merge;
// half-warp butterfly reduces both features of a warp simultaneously.
__global__ void __launch_bounds__(256) pool_k(const float* __restrict__ feat,
                                              float* __restrict__ out) {
    const int cell = blockIdx.x;
    const int warp = threadIdx.x >> 5;
    const int lane = threadIdx.x & 31;
    const int half = lane >> 4;        // which feature within the warp
    const int hlane = lane & 15;       // lane within the 16-lane feature group
    const int f = blockIdx.y * 16 + warp * 2 + half;

    const int y0    = g_hdr[cell][0];
    const int szy   = g_hdr[cell][1];
    const int x0a   = g_hdr[cell][2];
    const int bwa   = g_hdr[cell][3];
    const int x0off = g_hdr[cell][4];
    const int szx   = g_hdr[cell][5];

    // --- stage compact mask into shared memory (vectorized) ---
    __shared__ __align__(16) float smask[CMSTRIDE];
    {
        const int nq = (szy * bwa) >> 2;   // multiple of 4 guaranteed
        const float4* src = (const float4*)g_cmask[cell];
        float4* dst = (float4*)smask;
        for (int p = threadIdx.x; p < nq; p += 256) dst[p] = src[p];
    }
    __syncthreads();

    const int nG  = bwa >> 2;          // float4 groups per row: 3..10
    const int rpi = 16 / nG;           // rows per iteration: 1..5
    const int rowoff = hlane / nG;
    const int g = hlane - rowoff * nG;
    const bool active = (rowoff < rpi);

    const int b = cell >> 4;
    const float4* fbase = (const float4*)feat
        + (size_t)((b * F_ + f) * H_ + y0) * W4_ + (x0a >> 2) + g;
    const float4* mbase = (const float4*)smask + g;
    const int fstep = rpi * W4_;
    const int mstep = rpi * nG;

    // x-bin membership per (bin j, col k) — phase-invariant
    bool mem[12];
#pragma unroll
    for (int j = 0; j < 3; j++)
#pragma unroll
        for (int k = 0; k < 4; k++) {
            const int relx = g * 4 + k - x0off;
            mem[j * 4 + k] = (3 * relx >= j * szx - 2) && (3 * relx < (j + 1) * szx);
        }

    float bins[9];

#pragma unroll
    for (int i = 0; i < 3; i++) {
        const int ys = (i * szy) / 3;
        const int ye = ((i + 1) * szy + 2) / 3;   // ceil (bins may share a row)
        float a0 = -FLT_MAX, a1 = -FLT_MAX, a2 = -FLT_MAX, a3 = -FLT_MAX;
        if (active) {
            const float4* fp = fbase + (ys + rowoff) * W4_;
            const float4* mp = mbase + (ys + rowoff) * nG;
#pragma unroll 2
            for (int rr = ys + rowoff; rr < ye; rr += rpi, fp += fstep, mp += mstep) {
                const float4 fv = __ldg(fp);
                const float4 mv = *mp;          // LDS.128
                a0 = fmaxf(a0, fv.x * mv.x);
                a1 = fmaxf(a1, fv.y * mv.y);
                a2 = fmaxf(a2, fv.z * mv.z);
                a3 = fmaxf(a3, fv.w * mv.w);
            }
        }
#pragma unroll
        for (int j = 0; j < 3; j++) {
            float tb = -FLT_MAX;
            if (mem[j * 4 + 0]) tb = fmaxf(tb, a0);
            if (mem[j * 4 + 1]) tb = fmaxf(tb, a1);
            if (mem[j * 4 + 2]) tb = fmaxf(tb, a2);
            if (mem[j * 4 + 3]) tb = fmaxf(tb, a3);
            bins[i * 3 + j] = tb;
        }
    }

    // 4-stage butterfly within each half-warp: reduces both features at once
#pragma unroll
    for (int q = 0; q < 9; q++) {
        float v = bins[q];
#pragma unroll
        for (int o = 8; o > 0; o >>= 1)
            v = fmaxf(v, __shfl_xor_sync(0xffffffffu, v, o));
        bins[q] = v;
    }

    if (hlane < 9) {
        float v = bins[0];
#pragma unroll
        for (int q = 1; q < 9; q++)
            if (hlane == q) v = bins[q];
        out[(size_t)cell * (F_ * 9) + f * 9 + hlane] = v;
    }
}

// ---------------------------------------------------------------------------
extern "C" void kernel_launch(void* const* d_in, const int* in_sizes, int n_in,
                              void* d_out, int out_size) {
    const float* feat = (const float*)d_in[0];
    const void*  mask = d_in[1];
    float* out = (float*)d_out;

    prep_k<<<NCELL, 256>>>(mask);
    dim3 grid(NCELL, F_ / 16);
    pool_k<<<grid, 256>>>(feat, out);
}

// round 5
// speedup vs baseline: 1.5279x; 1.2393x over previous
#include <cuda_runtime.h>
#include <cstdint>
#include <float.h>
#include <limits.h>

// Problem constants (fixed shapes)
#define B_    8
#define C_    16
#define F_    256
#define H_    112
#define W_    112
#define NCELL (B_ * C_)       // 128
#define W4_   (W_ / 4)        // 28 float4 per feature row
#define PXPC  (H_ * W_)       // 12544 pixels per cell

// Compact mask scratch bounds: bbox w <= 35, +3 align +3 pad -> <= 40; h <= 35
#define MAXBW 40
#define MAXBH 36
#define CMSTRIDE (MAXBW * MAXBH)   // 1440 floats

// Per-cell header: y0, szy, x0a, bwa, x0off, szx
__device__ int g_hdr[NCELL][8];
// Per-cell compact float mask (1.0 / 0.0), row stride bwa, 16B aligned rows
__device__ __align__(16) float g_cmask[NCELL][CMSTRIDE];

// ---------------------------------------------------------------------------
// Fused prep: per-cell dtype detect + bbox + compact float mask. 1 block/cell.
//
// dtype detection is per-block-local and safe: every cell has a solid 5x5 core,
// so under uint8 the cell's own 12544-byte window contains packed-01 words
// (high bytes set, != 0x3F800000) -> flag=1. Under int32 OR float32, words are
// {0,1} or {0,0x3F800000} -> flag=0, and the 4-byte path treats "word != 0" as
// set, which is correct for both encodings.
__global__ void __launch_bounds__(256) prep_k(const void* __restrict__ mask) {
    const int cell = blockIdx.x;
    const int t = threadIdx.x;

    __shared__ int sy0, sy1, sx0, sx1;
    if (t == 0) { sy0 = INT_MAX; sy1 = -1; sx0 = INT_MAX; sx1 = -1; }

    // --- detect over this cell's 12544-byte window (784 uint4) ---
    int r = 0;
    {
        const uint4* wq = (const uint4*)mask + (size_t)cell * 784;
        for (int i = t; i < 784; i += 256) {
            uint4 w = wq[i];
            if ((w.x != 0x3F800000u && (w.x & 0xFFFFFF00u)) ||
                (w.y != 0x3F800000u && (w.y & 0xFFFFFF00u)) ||
                (w.z != 0x3F800000u && (w.z & 0xFFFFFF00u)) ||
                (w.w != 0x3F800000u && (w.w & 0xFFFFFF00u))) r = 1;
        }
    }
    const int flag = __syncthreads_or(r);   // also orders the smem init above

    // --- bbox scan ---
    int ly0 = INT_MAX, ly1 = -1, lx0 = INT_MAX, lx1 = -1;
    if (flag) {
        // uint8: 784 uint4 = 16 px each; 112 % 16 == 0 -> one row per vector
        const uint4* mq = (const uint4*)mask + (size_t)cell * 784;
        for (int i = t; i < 784; i += 256) {
            uint4 w = mq[i];
            if (w.x | w.y | w.z | w.w) {
                int p = i * 16, y = p / W_, xb = p % W_;
                ly0 = min(ly0, y); ly1 = max(ly1, y);
                unsigned int comp[4] = {w.x, w.y, w.z, w.w};
#pragma unroll
                for (int c = 0; c < 4; c++) {
#pragma unroll
                    for (int k = 0; k < 4; k++) {
                        if ((comp[c] >> (k * 8)) & 0xFFu) {
                            int x = xb + c * 4 + k;
                            lx0 = min(lx0, x); lx1 = max(lx1, x);
                        }
                    }
                }
            }
        }
    } else {
        // 4-byte: 3136 uint4 = 4 px each; 112 % 4 == 0 -> one row per vector
        const uint4* mq = (const uint4*)mask + (size_t)cell * 3136;
        for (int i = t; i < 3136; i += 256) {
            uint4 w = mq[i];
            if (w.x | w.y | w.z | w.w) {
                int p = i * 4, y = p / W_, xb = p % W_;
                ly0 = min(ly0, y); ly1 = max(ly1, y);
                if (w.x) { lx0 = min(lx0, xb);     lx1 = max(lx1, xb);     }
                if (w.y) { lx0 = min(lx0, xb + 1); lx1 = max(lx1, xb + 1); }
                if (w.z) { lx0 = min(lx0, xb + 2); lx1 = max(lx1, xb + 2); }
                if (w.w) { lx0 = min(lx0, xb + 3); lx1 = max(lx1, xb + 3); }
            }
        }
    }
    if (ly1 >= 0) {
        atomicMin(&sy0, ly0); atomicMax(&sy1, ly1);
        atomicMin(&sx0, lx0); atomicMax(&sx1, lx1);
    }
    __syncthreads();

    const int y0 = sy0, y1 = sy1 + 1, x0 = sx0, x1 = sx1 + 1;
    const int x0a = x0 & ~3;
    const int bwa = (x1 - x0a + 3) & ~3;
    const int bh  = y1 - y0;

    if (t == 0) {
        g_hdr[cell][0] = y0;
        g_hdr[cell][1] = bh;
        g_hdr[cell][2] = x0a;
        g_hdr[cell][3] = bwa;
        g_hdr[cell][4] = x0 - x0a;
        g_hdr[cell][5] = x1 - x0;
    }

    // --- compact float mask (pad cols read real data; excluded by membership) ---
    const int ntot = bh * bwa;
    const uint8_t* mb = (const uint8_t*)mask + (size_t)cell * PXPC;
    const int*     mi = (const int*)mask     + (size_t)cell * PXPC;
    for (int p = t; p < ntot; p += 256) {
        int rr = p / bwa, c = p - rr * bwa;
        int gp = (y0 + rr) * W_ + (x0a + c);
        bool set = flag ? (mb[gp] != 0) : (mi[gp] != 0);
        g_cmask[cell][p] = set ? 1.0f : 0.0f;
    }
}

// ---------------------------------------------------------------------------
// Main pooling. grid=(NCELL, F/32), block=256 (8 warps). Each half-warp
// (16 lanes) processes TWO features (f, f+16) simultaneously: one shared
// LDS.128 mask read feeds two independent LDG.128 feature streams per
// iteration -> 2x memory-level parallelism per lane. 3 y-bin phases with
// register accumulators; x-bins resolved at merge; half-warp butterfly.
__global__ void __launch_bounds__(256, 4) pool_k(const float* __restrict__ feat,
                                                 float* __restrict__ out) {
    const int cell = blockIdx.x;
    const int warp = threadIdx.x >> 5;
    const int lane = threadIdx.x & 31;
    const int half = lane >> 4;
    const int hlane = lane & 15;
    const int f0 = blockIdx.y * 32 + warp * 2 + half;   // second feature = f0+16

    const int y0    = g_hdr[cell][0];
    const int szy   = g_hdr[cell][1];
    const int x0a   = g_hdr[cell][2];
    const int bwa   = g_hdr[cell][3];
    const int x0off = g_hdr[cell][4];
    const int szx   = g_hdr[cell][5];

    // --- stage compact mask into shared memory (vectorized) ---
    __shared__ __align__(16) float smask[CMSTRIDE];
    {
        const int nq = (szy * bwa) >> 2;
        const float4* src = (const float4*)g_cmask[cell];
        float4* dst = (float4*)smask;
        for (int p = threadIdx.x; p < nq; p += 256) dst[p] = src[p];
    }
    __syncthreads();

    const int nG  = bwa >> 2;          // float4 groups per row: 3..10
    const int rpi = 16 / nG;           // rows per iteration: 1..5
    const int rowoff = hlane / nG;
    const int g = hlane - rowoff * nG;
    const bool active = (rowoff < rpi);

    const int b = cell >> 4;
    const float4* fbase = (const float4*)feat
        + (size_t)((b * F_ + f0) * H_ + y0) * W4_ + (x0a >> 2) + g;
    const int FOFF = 16 * H_ * W4_;    // float4 offset between f0 and f0+16
    const float4* mbase = (const float4*)smask + g;
    const int fstep = rpi * W4_;
    const int mstep = rpi * nG;

    // x-bin membership per (bin j, col k) — phase-invariant
    bool mem[12];
#pragma unroll
    for (int j = 0; j < 3; j++)
#pragma unroll
        for (int k = 0; k < 4; k++) {
            const int relx = g * 4 + k - x0off;
            mem[j * 4 + k] = (3 * relx >= j * szx - 2) && (3 * relx < (j + 1) * szx);
        }

    float binsA[9], binsB[9];

#pragma unroll
    for (int i = 0; i < 3; i++) {
        const int ys = (i * szy) / 3;
        const int ye = ((i + 1) * szy + 2) / 3;   // ceil (bins may share a row)
        float a0 = -FLT_MAX, a1 = -FLT_MAX, a2 = -FLT_MAX, a3 = -FLT_MAX;
        float b0 = -FLT_MAX, b1 = -FLT_MAX, b2 = -FLT_MAX, b3 = -FLT_MAX;
        if (active) {
            const float4* fp = fbase + (ys + rowoff) * W4_;
            const float4* mp = mbase + (ys + rowoff) * nG;
#pragma unroll 2
            for (int rr = ys + rowoff; rr < ye; rr += rpi, fp += fstep, mp += mstep) {
                const float4 fva = __ldg(fp);
                const float4 fvb = __ldg(fp + FOFF);
                const float4 mv = *mp;          // LDS.128
                a0 = fmaxf(a0, fva.x * mv.x);
                a1 = fmaxf(a1, fva.y * mv.y);
                a2 = fmaxf(a2, fva.z * mv.z);
                a3 = fmaxf(a3, fva.w * mv.w);
                b0 = fmaxf(b0, fvb.x * mv.x);
                b1 = fmaxf(b1, fvb.y * mv.y);
                b2 = fmaxf(b2, fvb.z * mv.z);
                b3 = fmaxf(b3, fvb.w * mv.w);
            }
        }
#pragma unroll
        for (int j = 0; j < 3; j++) {
            float ta = -FLT_MAX, tb = -FLT_MAX;
            if (mem[j * 4 + 0]) { ta = fmaxf(ta, a0); tb = fmaxf(tb, b0); }
            if (mem[j * 4 + 1]) { ta = fmaxf(ta, a1); tb = fmaxf(tb, b1); }
            if (mem[j * 4 + 2]) { ta = fmaxf(ta, a2); tb = fmaxf(tb, b2); }
            if (mem[j * 4 + 3]) { ta = fmaxf(ta, a3); tb = fmaxf(tb, b3); }
            binsA[i * 3 + j] = ta;
            binsB[i * 3 + j] = tb;
        }
    }

    // 4-stage butterfly within each half-warp (both features, all 18 values)
#pragma unroll
    for (int q = 0; q < 9; q++) {
        float va = binsA[q], vb = binsB[q];
#pragma unroll
        for (int o = 8; o > 0; o >>= 1) {
            va = fmaxf(va, __shfl_xor_sync(0xffffffffu, va, o));
            vb = fmaxf(vb, __shfl_xor_sync(0xffffffffu, vb, o));
        }
        binsA[q] = va; binsB[q] = vb;
    }

    if (hlane < 9) {
        float va = binsA[0], vb = binsB[0];
#pragma unroll
        for (int q = 1; q < 9; q++)
            if (hlane == q) { va = binsA[q]; vb = binsB[q]; }
        float* o = out + (size_t)cell * (F_ * 9) + f0 * 9 + hlane;
        o[0] = va;
        o[16 * 9] = vb;
    }
}

// ---------------------------------------------------------------------------
extern "C" void kernel_launch(void* const* d_in, const int* in_sizes, int n_in,
                              void* d_out, int out_size) {
    const float* feat = (const float*)d_in[0];
    const void*  mask = d_in[1];
    float* out = (float*)d_out;

    prep_k<<<NCELL, 256>>>(mask);
    dim3 grid(NCELL, F_ / 32);
    pool_k<<<grid, 256>>>(feat, out);
}

// round 6
// speedup vs baseline: 1.6773x; 1.0978x over previous
#include <cuda_runtime.h>
#include <cstdint>
#include <float.h>
#include <limits.h>

// Problem constants (fixed shapes)
#define B_    8
#define C_    16
#define F_    256
#define H_    112
#define W_    112
#define NCELL (B_ * C_)       // 128
#define W4_   (W_ / 4)        // 28 float4 per feature row
#define PXPC  (H_ * W_)       // 12544 pixels per cell

// Compact mask scratch bounds: bbox w <= 35, +3 align +3 pad -> <= 40; h <= 35
#define MAXBW 40
#define MAXBH 36
#define CMSTRIDE (MAXBW * MAXBH)   // 1440 floats

// Per-cell header: y0, szy, x0a, bwa, x0off, szx
__device__ int g_hdr[NCELL][8];
// Per-cell compact float mask (1.0 / 0.0), row stride bwa, 16B aligned rows
__device__ __align__(16) float g_cmask[NCELL][CMSTRIDE];

// ---------------------------------------------------------------------------
// Fused prep: per-cell dtype detect + bbox + compact float mask. 1 block/cell.
// (unchanged from round 4 — measured ~1.5-2us total overhead)
__global__ void __launch_bounds__(256) prep_k(const void* __restrict__ mask) {
    const int cell = blockIdx.x;
    const int t = threadIdx.x;

    __shared__ int sy0, sy1, sx0, sx1;
    if (t == 0) { sy0 = INT_MAX; sy1 = -1; sx0 = INT_MAX; sx1 = -1; }

    // --- detect over this cell's 12544-byte window (784 uint4) ---
    int r = 0;
    {
        const uint4* wq = (const uint4*)mask + (size_t)cell * 784;
        for (int i = t; i < 784; i += 256) {
            uint4 w = wq[i];
            if ((w.x != 0x3F800000u && (w.x & 0xFFFFFF00u)) ||
                (w.y != 0x3F800000u && (w.y & 0xFFFFFF00u)) ||
                (w.z != 0x3F800000u && (w.z & 0xFFFFFF00u)) ||
                (w.w != 0x3F800000u && (w.w & 0xFFFFFF00u))) r = 1;
        }
    }
    const int flag = __syncthreads_or(r);

    // --- bbox scan ---
    int ly0 = INT_MAX, ly1 = -1, lx0 = INT_MAX, lx1 = -1;
    if (flag) {
        const uint4* mq = (const uint4*)mask + (size_t)cell * 784;
        for (int i = t; i < 784; i += 256) {
            uint4 w = mq[i];
            if (w.x | w.y | w.z | w.w) {
                int p = i * 16, y = p / W_, xb = p % W_;
                ly0 = min(ly0, y); ly1 = max(ly1, y);
                unsigned int comp[4] = {w.x, w.y, w.z, w.w};
#pragma unroll
                for (int c = 0; c < 4; c++) {
#pragma unroll
                    for (int k = 0; k < 4; k++) {
                        if ((comp[c] >> (k * 8)) & 0xFFu) {
                            int x = xb + c * 4 + k;
                            lx0 = min(lx0, x); lx1 = max(lx1, x);
                        }
                    }
                }
            }
        }
    } else {
        const uint4* mq = (const uint4*)mask + (size_t)cell * 3136;
        for (int i = t; i < 3136; i += 256) {
            uint4 w = mq[i];
            if (w.x | w.y | w.z | w.w) {
                int p = i * 4, y = p / W_, xb = p % W_;
                ly0 = min(ly0, y); ly1 = max(ly1, y);
                if (w.x) { lx0 = min(lx0, xb);     lx1 = max(lx1, xb);     }
                if (w.y) { lx0 = min(lx0, xb + 1); lx1 = max(lx1, xb + 1); }
                if (w.z) { lx0 = min(lx0, xb + 2); lx1 = max(lx1, xb + 2); }
                if (w.w) { lx0 = min(lx0, xb + 3); lx1 = max(lx1, xb + 3); }
            }
        }
    }
    if (ly1 >= 0) {
        atomicMin(&sy0, ly0); atomicMax(&sy1, ly1);
        atomicMin(&sx0, lx0); atomicMax(&sx1, lx1);
    }
    __syncthreads();

    const int y0 = sy0, y1 = sy1 + 1, x0 = sx0, x1 = sx1 + 1;
    const int x0a = x0 & ~3;
    const int bwa = (x1 - x0a + 3) & ~3;
    const int bh  = y1 - y0;

    if (t == 0) {
        g_hdr[cell][0] = y0;
        g_hdr[cell][1] = bh;
        g_hdr[cell][2] = x0a;
        g_hdr[cell][3] = bwa;
        g_hdr[cell][4] = x0 - x0a;
        g_hdr[cell][5] = x1 - x0;
    }

    const int ntot = bh * bwa;
    const uint8_t* mb = (const uint8_t*)mask + (size_t)cell * PXPC;
    const int*     mi = (const int*)mask     + (size_t)cell * PXPC;
    for (int p = t; p < ntot; p += 256) {
        int rr = p / bwa, c = p - rr * bwa;
        int gp = (y0 + rr) * W_ + (x0a + c);
        bool set = flag ? (mb[gp] != 0) : (mi[gp] != 0);
        g_cmask[cell][p] = set ? 1.0f : 0.0f;
    }
}

// ---------------------------------------------------------------------------
// Main pooling. grid=(NCELL, F/64), block=256 (8 warps). Each half-warp
// (16 lanes) processes FOUR features (f0, f0+16, f0+32, f0+48): one LDS.128
// mask read feeds 4 independent LDG.128 feature streams per iteration.
// 3 y-bin phases; after each phase, each x-bin is butterfly-reduced and
// stored immediately (no bins[] arrays held across phases -> low reg count).
__global__ void __launch_bounds__(256, 4) pool_k(const float* __restrict__ feat,
                                                 float* __restrict__ out) {
    const int cell = blockIdx.x;
    const int warp = threadIdx.x >> 5;
    const int lane = threadIdx.x & 31;
    const int half = lane >> 4;
    const int hlane = lane & 15;
    const int f0 = blockIdx.y * 64 + warp * 2 + half;   // streams: f0 + {0,16,32,48}

    const int y0    = g_hdr[cell][0];
    const int szy   = g_hdr[cell][1];
    const int x0a   = g_hdr[cell][2];
    const int bwa   = g_hdr[cell][3];
    const int x0off = g_hdr[cell][4];
    const int szx   = g_hdr[cell][5];

    // --- stage compact mask into shared memory (vectorized) ---
    __shared__ __align__(16) float smask[CMSTRIDE];
    {
        const int nq = (szy * bwa) >> 2;
        const float4* src = (const float4*)g_cmask[cell];
        float4* dst = (float4*)smask;
        for (int p = threadIdx.x; p < nq; p += 256) dst[p] = src[p];
    }
    __syncthreads();

    const int nG  = bwa >> 2;          // float4 groups per row: 3..10
    const int rpi = 16 / nG;           // rows per iteration: 1..5
    const int rowoff = hlane / nG;
    const int g = hlane - rowoff * nG;
    const bool active = (rowoff < rpi);

    const int b = cell >> 4;
    const int FOFF = 16 * H_ * W4_;    // float4 offset between feature streams
    const float4* fbase = (const float4*)feat
        + (size_t)((b * F_ + f0) * H_ + y0) * W4_ + (x0a >> 2) + g;
    const float4* mbase = (const float4*)smask + g;
    const int fstep = rpi * W4_;
    const int mstep = rpi * nG;

    // x-bin membership per (bin j, col k) — phase-invariant
    bool mem[12];
#pragma unroll
    for (int j = 0; j < 3; j++)
#pragma unroll
        for (int k = 0; k < 4; k++) {
            const int relx = g * 4 + k - x0off;
            mem[j * 4 + k] = (3 * relx >= j * szx - 2) && (3 * relx < (j + 1) * szx);
        }

    float* obase = out + (size_t)cell * (F_ * 9) + f0 * 9;

#pragma unroll
    for (int i = 0; i < 3; i++) {
        const int ys = (i * szy) / 3;
        const int ye = ((i + 1) * szy + 2) / 3;   // ceil (bins may share a row)

        float acc[4][4];
#pragma unroll
        for (int s = 0; s < 4; s++)
#pragma unroll
            for (int k = 0; k < 4; k++) acc[s][k] = -FLT_MAX;

        if (active) {
            const float4* fp = fbase + (ys + rowoff) * W4_;
            const float4* mp = mbase + (ys + rowoff) * nG;
#pragma unroll 2
            for (int rr = ys + rowoff; rr < ye; rr += rpi, fp += fstep, mp += mstep) {
                const float4 mv = *mp;          // LDS.128
                float4 fv[4];
                fv[0] = __ldg(fp);
                fv[1] = __ldg(fp + FOFF);
                fv[2] = __ldg(fp + 2 * FOFF);
                fv[3] = __ldg(fp + 3 * FOFF);
#pragma unroll
                for (int s = 0; s < 4; s++) {
                    acc[s][0] = fmaxf(acc[s][0], fv[s].x * mv.x);
                    acc[s][1] = fmaxf(acc[s][1], fv[s].y * mv.y);
                    acc[s][2] = fmaxf(acc[s][2], fv[s].z * mv.z);
                    acc[s][3] = fmaxf(acc[s][3], fv[s].w * mv.w);
                }
            }
        }

        // per x-bin: merge columns, butterfly across the 16-lane group, store
#pragma unroll
        for (int j = 0; j < 3; j++) {
            float t0 = -FLT_MAX, t1 = -FLT_MAX, t2 = -FLT_MAX, t3 = -FLT_MAX;
#pragma unroll
            for (int k = 0; k < 4; k++) {
                if (mem[j * 4 + k]) {
                    t0 = fmaxf(t0, acc[0][k]);
                    t1 = fmaxf(t1, acc[1][k]);
                    t2 = fmaxf(t2, acc[2][k]);
                    t3 = fmaxf(t3, acc[3][k]);
                }
            }
#pragma unroll
            for (int o = 8; o > 0; o >>= 1) {
                t0 = fmaxf(t0, __shfl_xor_sync(0xffffffffu, t0, o));
                t1 = fmaxf(t1, __shfl_xor_sync(0xffffffffu, t1, o));
                t2 = fmaxf(t2, __shfl_xor_sync(0xffffffffu, t2, o));
                t3 = fmaxf(t3, __shfl_xor_sync(0xffffffffu, t3, o));
            }
            if (hlane == j) {
                obase[i * 3 + j]              = t0;
                obase[16 * 9 + i * 3 + j]     = t1;
                obase[32 * 9 + i * 3 + j]     = t2;
                obase[48 * 9 + i * 3 + j]     = t3;
            }
        }
    }
}

// ---------------------------------------------------------------------------
extern "C" void kernel_launch(void* const* d_in, const int* in_sizes, int n_in,
                              void* d_out, int out_size) {
    const float* feat = (const float*)d_in[0];
    const void*  mask = d_in[1];
    float* out = (float*)d_out;

    prep_k<<<NCELL, 256>>>(mask);
    dim3 grid(NCELL, F_ / 64);
    pool_k<<<grid, 256>>>(feat, out);
}